// round 1
// baseline (speedup 1.0000x reference)
#include <cuda_runtime.h>
#include <math.h>

#define BATCH   2
#define S_LEN   2048
#define D_MODEL 1024
#define NHEAD   16
#define HDIM    64
#define LN_EPS  1e-5f

// ---------------------------------------------------------------------------
// Scratch (device globals: allocation-free rule)
// ---------------------------------------------------------------------------
__device__ float g_Q[BATCH * NHEAD * S_LEN * HDIM];   // [B,H,S,hd]
__device__ float g_K[BATCH * NHEAD * S_LEN * HDIM];
__device__ float g_V[BATCH * NHEAD * S_LEN * HDIM];
__device__ float g_O[BATCH * S_LEN * D_MODEL];        // attention out, [B,S,D]

// ---------------------------------------------------------------------------
// QKV projection GEMM: Y[m,n] = sum_k X[m,k] * W[n,k] + bias[n]
// M = B*S = 4096, N = D = 1024, K = D = 1024
// Tile 64x64, K-chunk 16, 256 threads, 4x4 per thread.
// Output written into [B,H,S,hd] scratch selected by `which`.
// ---------------------------------------------------------------------------
__global__ __launch_bounds__(256)
void qkv_gemm_kernel(const float* __restrict__ X,
                     const float* __restrict__ W,
                     const float* __restrict__ bias,
                     int which)
{
    __shared__ float Xs[16][68];   // [k][m], padded
    __shared__ float Ws[16][68];   // [k][n], padded

    float* outp = (which == 0) ? g_Q : (which == 1) ? g_K : g_V;

    const int tid = threadIdx.x;
    const int tx  = tid & 15;      // n sub-tile
    const int ty  = tid >> 4;      // m sub-tile
    const int m0  = blockIdx.x * 64;
    const int n0  = blockIdx.y * 64;

    const int lr  = tid >> 2;          // 0..63: row within tile to load
    const int lc  = (tid & 3) * 4;     // 0,4,8,12: k offset (float4)

    float acc[4][4];
#pragma unroll
    for (int i = 0; i < 4; i++)
#pragma unroll
        for (int j = 0; j < 4; j++) acc[i][j] = 0.0f;

    for (int k0 = 0; k0 < D_MODEL; k0 += 16) {
        float4 xv = *(const float4*)(X + (size_t)(m0 + lr) * D_MODEL + k0 + lc);
        float4 wv = *(const float4*)(W + (size_t)(n0 + lr) * D_MODEL + k0 + lc);
        Xs[lc + 0][lr] = xv.x; Xs[lc + 1][lr] = xv.y;
        Xs[lc + 2][lr] = xv.z; Xs[lc + 3][lr] = xv.w;
        Ws[lc + 0][lr] = wv.x; Ws[lc + 1][lr] = wv.y;
        Ws[lc + 2][lr] = wv.z; Ws[lc + 3][lr] = wv.w;
        __syncthreads();

#pragma unroll
        for (int k = 0; k < 16; k++) {
            float a[4], b[4];
#pragma unroll
            for (int i = 0; i < 4; i++) a[i] = Xs[k][ty * 4 + i];
#pragma unroll
            for (int j = 0; j < 4; j++) b[j] = Ws[k][tx * 4 + j];
#pragma unroll
            for (int i = 0; i < 4; i++)
#pragma unroll
                for (int j = 0; j < 4; j++)
                    acc[i][j] += a[i] * b[j];
        }
        __syncthreads();
    }

    // Epilogue: n-tile is 64-aligned, so one head per block column.
    const int h = n0 >> 6;
#pragma unroll
    for (int i = 0; i < 4; i++) {
        const int m = m0 + ty * 4 + i;
        const int b = m >> 11;          // /2048
        const int s = m & 2047;
        float* orow = outp + (((size_t)(b * NHEAD + h) * S_LEN) + s) * HDIM;
#pragma unroll
        for (int j = 0; j < 4; j++) {
            const int n = n0 + tx * 4 + j;
            orow[n & 63] = acc[i][j] + bias[n];
        }
    }
}

// ---------------------------------------------------------------------------
// Flash attention (fp32). Grid: (S/64, B*H). Block: 64 threads.
// Thread t owns q-row (q0 + t): q[64], o[64] in registers.
// K/V tiles (64 x 64) and per-thread score rows staged in smem.
// ---------------------------------------------------------------------------
__global__ __launch_bounds__(64)
void attn_kernel()
{
    __shared__ float Ks[64][64];
    __shared__ float Vs[64][64];
    __shared__ float Ss[64][64];   // [j][tid] -> conflict-free

    const int tid = threadIdx.x;
    const int q0  = blockIdx.x * 64;
    const int bh  = blockIdx.y;

    const float* Qg = g_Q + ((size_t)bh * S_LEN + q0 + tid) * HDIM;
    const float* Kg = g_K + (size_t)bh * S_LEN * HDIM;
    const float* Vg = g_V + (size_t)bh * S_LEN * HDIM;

    float q[64], o[64];
#pragma unroll
    for (int d4 = 0; d4 < 16; d4++) {
        float4 t4 = *(const float4*)(Qg + d4 * 4);
        q[d4 * 4 + 0] = t4.x * 0.125f;   // 1/sqrt(64)
        q[d4 * 4 + 1] = t4.y * 0.125f;
        q[d4 * 4 + 2] = t4.z * 0.125f;
        q[d4 * 4 + 3] = t4.w * 0.125f;
    }
#pragma unroll
    for (int d = 0; d < 64; d++) o[d] = 0.0f;

    float m = -1e30f, l = 0.0f;

    for (int k0 = 0; k0 < S_LEN; k0 += 64) {
        // cooperative coalesced tile load (1024 float4 per matrix, 64 threads)
        const float4* Ksrc = (const float4*)(Kg + (size_t)k0 * HDIM);
        const float4* Vsrc = (const float4*)(Vg + (size_t)k0 * HDIM);
        float4* Kd = (float4*)&Ks[0][0];
        float4* Vd = (float4*)&Vs[0][0];
#pragma unroll
        for (int it = 0; it < 16; it++) {
            Kd[it * 64 + tid] = Ksrc[it * 64 + tid];
            Vd[it * 64 + tid] = Vsrc[it * 64 + tid];
        }
        __syncthreads();

        // scores for this tile
        float tmax = -1e30f;
#pragma unroll 2
        for (int j = 0; j < 64; j++) {
            const float4* kr = (const float4*)&Ks[j][0];
            float a0 = 0.f, a1 = 0.f, a2 = 0.f, a3 = 0.f;
#pragma unroll
            for (int d4 = 0; d4 < 16; d4++) {
                float4 kv = kr[d4];
                a0 += q[d4 * 4 + 0] * kv.x;
                a1 += q[d4 * 4 + 1] * kv.y;
                a2 += q[d4 * 4 + 2] * kv.z;
                a3 += q[d4 * 4 + 3] * kv.w;
            }
            float s = (a0 + a1) + (a2 + a3);
            Ss[j][tid] = s;
            tmax = fmaxf(tmax, s);
        }

        const float mnew = fmaxf(m, tmax);
        const float corr = __expf(m - mnew);
        l *= corr;
#pragma unroll
        for (int d = 0; d < 64; d++) o[d] *= corr;

#pragma unroll 2
        for (int j = 0; j < 64; j++) {
            const float p = __expf(Ss[j][tid] - mnew);
            l += p;
            const float4* vr = (const float4*)&Vs[j][0];
#pragma unroll
            for (int d4 = 0; d4 < 16; d4++) {
                float4 vv = vr[d4];
                o[d4 * 4 + 0] += p * vv.x;
                o[d4 * 4 + 1] += p * vv.y;
                o[d4 * 4 + 2] += p * vv.z;
                o[d4 * 4 + 3] += p * vv.w;
            }
        }
        m = mnew;
        __syncthreads();
    }

    const float inv = 1.0f / l;
    const int b = bh >> 4;
    const int h = bh & 15;
    float* og = g_O + ((size_t)b * S_LEN + q0 + tid) * D_MODEL + h * HDIM;
#pragma unroll
    for (int d4 = 0; d4 < 16; d4++) {
        float4 w4;
        w4.x = o[d4 * 4 + 0] * inv;
        w4.y = o[d4 * 4 + 1] * inv;
        w4.z = o[d4 * 4 + 2] * inv;
        w4.w = o[d4 * 4 + 3] * inv;
        *(float4*)(og + d4 * 4) = w4;
    }
}

// ---------------------------------------------------------------------------
// Residual + LayerNorm. Grid: B*S rows, 256 threads (1 float4 each).
// ---------------------------------------------------------------------------
__global__ __launch_bounds__(256)
void ln_kernel(const float* __restrict__ X,
               const float* __restrict__ gamma,
               const float* __restrict__ beta,
               float* __restrict__ out)
{
    const int row = blockIdx.x;
    const int tid = threadIdx.x;

    const float4 a = ((const float4*)(g_O + (size_t)row * D_MODEL))[tid];
    const float4 b = ((const float4*)(X   + (size_t)row * D_MODEL))[tid];
    float4 v;
    v.x = a.x + b.x; v.y = a.y + b.y; v.z = a.z + b.z; v.w = a.w + b.w;

    float s  = v.x + v.y + v.z + v.w;
    float ss = v.x * v.x + v.y * v.y + v.z * v.z + v.w * v.w;

#pragma unroll
    for (int off = 16; off > 0; off >>= 1) {
        s  += __shfl_xor_sync(0xffffffffu, s,  off);
        ss += __shfl_xor_sync(0xffffffffu, ss, off);
    }

    __shared__ float sh_s[8], sh_ss[8];
    const int w = tid >> 5, lane = tid & 31;
    if (lane == 0) { sh_s[w] = s; sh_ss[w] = ss; }
    __syncthreads();

    float tot = 0.f, tot2 = 0.f;
#pragma unroll
    for (int i = 0; i < 8; i++) { tot += sh_s[i]; tot2 += sh_ss[i]; }

    const float mean = tot * (1.0f / D_MODEL);
    const float var  = tot2 * (1.0f / D_MODEL) - mean * mean;
    const float rstd = rsqrtf(var + LN_EPS);

    const float4 gg = ((const float4*)gamma)[tid];
    const float4 bb = ((const float4*)beta)[tid];
    float4 r;
    r.x = (v.x - mean) * rstd * gg.x + bb.x;
    r.y = (v.y - mean) * rstd * gg.y + bb.y;
    r.z = (v.z - mean) * rstd * gg.z + bb.z;
    r.w = (v.w - mean) * rstd * gg.w + bb.w;
    ((float4*)out)[(size_t)row * (D_MODEL / 4) + tid] = r;
}

// ---------------------------------------------------------------------------
// Launch
// ---------------------------------------------------------------------------
extern "C" void kernel_launch(void* const* d_in, const int* in_sizes, int n_in,
                              void* d_out, int out_size)
{
    const float* x     = (const float*)d_in[0];
    const float* wq    = (const float*)d_in[1];
    const float* bq    = (const float*)d_in[2];
    const float* wk    = (const float*)d_in[3];
    const float* bk    = (const float*)d_in[4];
    const float* wv    = (const float*)d_in[5];
    const float* bv    = (const float*)d_in[6];
    const float* gamma = (const float*)d_in[7];
    const float* beta  = (const float*)d_in[8];
    float* out = (float*)d_out;

    dim3 ggrid(BATCH * S_LEN / 64, D_MODEL / 64);   // (64, 16)
    qkv_gemm_kernel<<<ggrid, 256>>>(x, wq, bq, 0);
    qkv_gemm_kernel<<<ggrid, 256>>>(x, wk, bk, 1);
    qkv_gemm_kernel<<<ggrid, 256>>>(x, wv, bv, 2);

    dim3 agrid(S_LEN / 64, BATCH * NHEAD);          // (32, 32)
    attn_kernel<<<agrid, 64>>>();

    ln_kernel<<<BATCH * S_LEN, 256>>>(x, gamma, beta, out);
}

// round 2
// speedup vs baseline: 2.9146x; 2.9146x over previous
#include <cuda_runtime.h>
#include <math.h>
#include <stdint.h>

#define BATCH   2
#define S_LEN   2048
#define D_MODEL 1024
#define NHEAD   16
#define HDIM    64
#define LN_EPS  1e-5f

#define BQ      128
#define BKV     128
#define KS_STRIDE 68
#define VS_STRIDE 72
#define PS_STRIDE 132
#define ATTN_SMEM ((BKV*KS_STRIDE + BKV*VS_STRIDE + BQ*PS_STRIDE) * 4)

// ---------------------------------------------------------------------------
// Scratch (device globals: allocation-free rule)
// Q/K/V are stored tf32-pre-rounded (bit patterns in float containers).
// ---------------------------------------------------------------------------
__device__ float g_Q[BATCH * NHEAD * S_LEN * HDIM];
__device__ float g_K[BATCH * NHEAD * S_LEN * HDIM];
__device__ float g_V[BATCH * NHEAD * S_LEN * HDIM];
__device__ float g_O[BATCH * S_LEN * D_MODEL];

// ---------------------------------------------------------------------------
// tf32 helpers
// ---------------------------------------------------------------------------
__device__ __forceinline__ unsigned f2tf(float x) {
    unsigned u;
    asm("cvt.rna.tf32.f32 %0, %1;" : "=r"(u) : "f"(x));
    return u;
}

__device__ __forceinline__ void mma8(float c[4], const unsigned a[4],
                                     unsigned b0, unsigned b1) {
    asm volatile(
        "mma.sync.aligned.m16n8k8.row.col.f32.tf32.tf32.f32 "
        "{%0,%1,%2,%3},{%4,%5,%6,%7},{%8,%9},{%0,%1,%2,%3};\n"
        : "+f"(c[0]), "+f"(c[1]), "+f"(c[2]), "+f"(c[3])
        : "r"(a[0]), "r"(a[1]), "r"(a[2]), "r"(a[3]), "r"(b0), "r"(b1));
}

// ---------------------------------------------------------------------------
// Fused QKV projection GEMM (tf32 MMA).
// Y[m,n] = sum_k X[m,k] * W[n,k] + bias[n]   (Q additionally scaled by 0.125)
// M=4096, N=1024, K=1024. CTA tile 128x128, BK=16, 8 warps (64x32 each).
// grid = (8, 32, 3); z selects Q/K/V. Output stored tf32-rounded to scratch
// in [B,H,S,hd] layout.
// ---------------------------------------------------------------------------
__global__ __launch_bounds__(256, 1)
void qkv_gemm(const float* __restrict__ X,
              const float* __restrict__ Wq, const float* __restrict__ bq,
              const float* __restrict__ Wk, const float* __restrict__ bk,
              const float* __restrict__ Wv, const float* __restrict__ bv)
{
    __shared__ float As[128 * 20];   // [m][k] stride 20 -> conflict-free frags
    __shared__ float Bs[128 * 20];   // [n][k] stride 20

    const int z = blockIdx.z;
    const float* W    = (z == 0) ? Wq : (z == 1) ? Wk : Wv;
    const float* bias = (z == 0) ? bq : (z == 1) ? bk : bv;
    float* out        = (z == 0) ? g_Q : (z == 1) ? g_K : g_V;
    const float scale = (z == 0) ? 0.125f : 1.0f;   // fold 1/sqrt(64) into Q

    const int t    = threadIdx.x;
    const int w    = t >> 5, lane = t & 31;
    const int qh   = lane >> 2, r = lane & 3;
    const int wm   = w >> 2, wn = w & 3;            // warp grid 2(m) x 4(n)
    const int m0   = blockIdx.y * 128;
    const int n0   = blockIdx.x * 128;

    const int lrow = t >> 1;                        // 0..127
    const int lk   = (t & 1) * 8;                   // 0 or 8

    const float* xp = X + (size_t)(m0 + lrow) * D_MODEL + lk;
    const float* wp = W + (size_t)(n0 + lrow) * D_MODEL + lk;

    float4 xa = *(const float4*)xp;
    float4 xb = *(const float4*)(xp + 4);
    float4 wa = *(const float4*)wp;
    float4 wb = *(const float4*)(wp + 4);

    float acc[4][4][4];
#pragma unroll
    for (int i = 0; i < 4; i++)
#pragma unroll
        for (int j = 0; j < 4; j++)
#pragma unroll
            for (int k = 0; k < 4; k++) acc[i][j][k] = 0.0f;

    unsigned* Au = (unsigned*)As;
    unsigned* Bu = (unsigned*)Bs;
    const int sbase = lrow * 20 + lk;

    for (int k0 = 0; k0 < D_MODEL; k0 += 16) {
        uint4 u;
        u.x = f2tf(xa.x); u.y = f2tf(xa.y); u.z = f2tf(xa.z); u.w = f2tf(xa.w);
        *(uint4*)&Au[sbase] = u;
        u.x = f2tf(xb.x); u.y = f2tf(xb.y); u.z = f2tf(xb.z); u.w = f2tf(xb.w);
        *(uint4*)&Au[sbase + 4] = u;
        u.x = f2tf(wa.x); u.y = f2tf(wa.y); u.z = f2tf(wa.z); u.w = f2tf(wa.w);
        *(uint4*)&Bu[sbase] = u;
        u.x = f2tf(wb.x); u.y = f2tf(wb.y); u.z = f2tf(wb.z); u.w = f2tf(wb.w);
        *(uint4*)&Bu[sbase + 4] = u;
        __syncthreads();

        if (k0 + 16 < D_MODEL) {   // prefetch next tile (overlap with MMA)
            xa = *(const float4*)(xp + k0 + 16);
            xb = *(const float4*)(xp + k0 + 20);
            wa = *(const float4*)(wp + k0 + 16);
            wb = *(const float4*)(wp + k0 + 20);
        }

#pragma unroll
        for (int kk = 0; kk < 16; kk += 8) {
            unsigned a[4][4];
#pragma unroll
            for (int i = 0; i < 4; i++) {
                const int rw = (wm * 64 + 16 * i + qh) * 20 + kk + r;
                a[i][0] = Au[rw];
                a[i][1] = Au[rw + 8 * 20];
                a[i][2] = Au[rw + 4];
                a[i][3] = Au[rw + 8 * 20 + 4];
            }
#pragma unroll
            for (int j = 0; j < 4; j++) {
                const int rwb = (wn * 32 + 8 * j + qh) * 20 + kk + r;
                const unsigned b0 = Bu[rwb];
                const unsigned b1 = Bu[rwb + 4];
#pragma unroll
                for (int i = 0; i < 4; i++) mma8(acc[i][j], a[i], b0, b1);
            }
        }
        __syncthreads();
    }

    // Epilogue: +bias, scale, tf32-round, scatter to [B,H,S,hd]
#pragma unroll
    for (int j = 0; j < 4; j++) {
        const int n = n0 + wn * 32 + 8 * j + 2 * r;
        const float2 bv2 = *(const float2*)(bias + n);
        const int h = n >> 6, hd = n & 63;
#pragma unroll
        for (int i = 0; i < 4; i++) {
            const int m = m0 + wm * 64 + 16 * i + qh;
            {
                const int b = m >> 11, s = m & 2047;
                float* p = out + (((size_t)(b * NHEAD + h) * S_LEN) + s) * HDIM + hd;
                uint2 o2;
                o2.x = f2tf((acc[i][j][0] + bv2.x) * scale);
                o2.y = f2tf((acc[i][j][1] + bv2.y) * scale);
                *(uint2*)p = o2;
            }
            {
                const int m2 = m + 8;
                const int b = m2 >> 11, s = m2 & 2047;
                float* p = out + (((size_t)(b * NHEAD + h) * S_LEN) + s) * HDIM + hd;
                uint2 o2;
                o2.x = f2tf((acc[i][j][2] + bv2.x) * scale);
                o2.y = f2tf((acc[i][j][3] + bv2.y) * scale);
                *(uint2*)p = o2;
            }
        }
    }
}

// ---------------------------------------------------------------------------
// Flash attention with tf32 MMA.
// Grid (16, 32): (q-block of 128, b*h). 256 threads, 8 warps.
// Warp w owns q rows [q0+16w, q0+16w+16): Q frags cached in registers,
// S accum 64 regs, O accum 32 regs. P round-trips through warp-private smem.
// ---------------------------------------------------------------------------
__global__ __launch_bounds__(256, 1)
void attn_mma()
{
    extern __shared__ float sm[];
    float* Ks = sm;                          // [kv][d]  stride 68
    float* Vs = Ks + BKV * KS_STRIDE;        // [kv][d]  stride 72
    float* Ps = Vs + BKV * VS_STRIDE;        // [q][kv]  stride 132
    unsigned* Ku = (unsigned*)Ks;
    unsigned* Vu = (unsigned*)Vs;
    unsigned* Pu = (unsigned*)Ps;

    const int t = threadIdx.x, w = t >> 5, lane = t & 31;
    const int qh = lane >> 2, r = lane & 3;
    const int q0 = blockIdx.x * BQ;
    const int bh = blockIdx.y;

    // Q fragments (already tf32-rounded & scaled by 0.125 in scratch)
    const float* Qg = g_Q + ((size_t)bh * S_LEN + q0 + 16 * w) * HDIM;
    unsigned qa[8][4];
#pragma unroll
    for (int kd = 0; kd < 8; kd++) {
        qa[kd][0] = __float_as_uint(Qg[qh * 64 + 8 * kd + r]);
        qa[kd][1] = __float_as_uint(Qg[(qh + 8) * 64 + 8 * kd + r]);
        qa[kd][2] = __float_as_uint(Qg[qh * 64 + 8 * kd + r + 4]);
        qa[kd][3] = __float_as_uint(Qg[(qh + 8) * 64 + 8 * kd + r + 4]);
    }

    float o[8][4];
#pragma unroll
    for (int j = 0; j < 8; j++)
#pragma unroll
        for (int k = 0; k < 4; k++) o[j][k] = 0.0f;
    float m0 = -1e30f, m1 = -1e30f, l0 = 0.0f, l1 = 0.0f;

    const float* Kg = g_K + (size_t)bh * S_LEN * HDIM;
    const float* Vg = g_V + (size_t)bh * S_LEN * HDIM;

    const int prow0 = (16 * w + qh) * PS_STRIDE;
    const int prow1 = prow0 + 8 * PS_STRIDE;

    for (int kv0 = 0; kv0 < S_LEN; kv0 += BKV) {
        // cooperative K/V tile load (coalesced float4)
#pragma unroll
        for (int i = 0; i < 8; i++) {
            const int idx = i * 256 + t;
            const int row = idx >> 4, c4 = (idx & 15) * 4;
            *(float4*)&Ks[row * KS_STRIDE + c4] =
                *(const float4*)(Kg + (size_t)(kv0 + row) * HDIM + c4);
            *(float4*)&Vs[row * VS_STRIDE + c4] =
                *(const float4*)(Vg + (size_t)(kv0 + row) * HDIM + c4);
        }
        __syncthreads();

        // ---- S = Q @ K^T (scaled) ----
        float s[16][4];
#pragma unroll
        for (int j = 0; j < 16; j++)
#pragma unroll
            for (int k = 0; k < 4; k++) s[j][k] = 0.0f;

#pragma unroll
        for (int kd = 0; kd < 8; kd++) {
#pragma unroll
            for (int j = 0; j < 16; j++) {
                const int a = (8 * j + qh) * KS_STRIDE + 8 * kd + r;
                mma8(s[j], qa[kd], Ku[a], Ku[a + 4]);
            }
        }

        // ---- online softmax ----
        float mx0 = -1e30f, mx1 = -1e30f;
#pragma unroll
        for (int j = 0; j < 16; j++) {
            mx0 = fmaxf(mx0, fmaxf(s[j][0], s[j][1]));
            mx1 = fmaxf(mx1, fmaxf(s[j][2], s[j][3]));
        }
        mx0 = fmaxf(mx0, __shfl_xor_sync(0xffffffffu, mx0, 1));
        mx0 = fmaxf(mx0, __shfl_xor_sync(0xffffffffu, mx0, 2));
        mx1 = fmaxf(mx1, __shfl_xor_sync(0xffffffffu, mx1, 1));
        mx1 = fmaxf(mx1, __shfl_xor_sync(0xffffffffu, mx1, 2));

        const float n0_ = fmaxf(m0, mx0), n1_ = fmaxf(m1, mx1);
        const float c0 = __expf(m0 - n0_), c1 = __expf(m1 - n1_);
        m0 = n0_; m1 = n1_;

        float rs0 = 0.0f, rs1 = 0.0f;
#pragma unroll
        for (int j = 0; j < 16; j++) {
            s[j][0] = __expf(s[j][0] - m0);
            s[j][1] = __expf(s[j][1] - m0);
            rs0 += s[j][0] + s[j][1];
            s[j][2] = __expf(s[j][2] - m1);
            s[j][3] = __expf(s[j][3] - m1);
            rs1 += s[j][2] + s[j][3];
        }
        rs0 += __shfl_xor_sync(0xffffffffu, rs0, 1);
        rs0 += __shfl_xor_sync(0xffffffffu, rs0, 2);
        rs1 += __shfl_xor_sync(0xffffffffu, rs1, 1);
        rs1 += __shfl_xor_sync(0xffffffffu, rs1, 2);
        l0 = l0 * c0 + rs0;
        l1 = l1 * c1 + rs1;

#pragma unroll
        for (int j = 0; j < 8; j++) {
            o[j][0] *= c0; o[j][1] *= c0;
            o[j][2] *= c1; o[j][3] *= c1;
        }

        // ---- P -> warp-private smem (tf32) ----
#pragma unroll
        for (int j = 0; j < 16; j++) {
            uint2 u0; u0.x = f2tf(s[j][0]); u0.y = f2tf(s[j][1]);
            *(uint2*)&Pu[prow0 + 8 * j + 2 * r] = u0;
            uint2 u1; u1.x = f2tf(s[j][2]); u1.y = f2tf(s[j][3]);
            *(uint2*)&Pu[prow1 + 8 * j + 2 * r] = u1;
        }
        __syncwarp();

        // ---- O += P @ V ----
#pragma unroll
        for (int kf = 0; kf < 16; kf++) {
            unsigned a[4];
            a[0] = Pu[prow0 + 8 * kf + r];
            a[1] = Pu[prow1 + 8 * kf + r];
            a[2] = Pu[prow0 + 8 * kf + r + 4];
            a[3] = Pu[prow1 + 8 * kf + r + 4];
#pragma unroll
            for (int j = 0; j < 8; j++) {
                const int vb = (8 * kf + r) * VS_STRIDE + 8 * j + qh;
                mma8(o[j], a, Vu[vb], Vu[vb + 4 * VS_STRIDE]);
            }
        }
        __syncthreads();
    }

    // epilogue: O / l -> g_O [B,S,D]
    const float i0 = 1.0f / l0, i1 = 1.0f / l1;
    const int b = bh >> 4, h = bh & 15;
    const int row0 = q0 + 16 * w + qh;
    float* G0 = g_O + ((size_t)b * S_LEN + row0) * D_MODEL + h * HDIM;
    float* G1 = G0 + 8 * D_MODEL;
#pragma unroll
    for (int j = 0; j < 8; j++) {
        const int cc = 8 * j + 2 * r;
        float2 v0; v0.x = o[j][0] * i0; v0.y = o[j][1] * i0;
        *(float2*)(G0 + cc) = v0;
        float2 v1; v1.x = o[j][2] * i1; v1.y = o[j][3] * i1;
        *(float2*)(G1 + cc) = v1;
    }
}

// ---------------------------------------------------------------------------
// Residual + LayerNorm. Grid: B*S rows, 256 threads (1 float4 each).
// ---------------------------------------------------------------------------
__global__ __launch_bounds__(256)
void ln_kernel(const float* __restrict__ X,
               const float* __restrict__ gamma,
               const float* __restrict__ beta,
               float* __restrict__ out)
{
    const int row = blockIdx.x;
    const int tid = threadIdx.x;

    const float4 a = ((const float4*)(g_O + (size_t)row * D_MODEL))[tid];
    const float4 b = ((const float4*)(X   + (size_t)row * D_MODEL))[tid];
    float4 v;
    v.x = a.x + b.x; v.y = a.y + b.y; v.z = a.z + b.z; v.w = a.w + b.w;

    float s  = v.x + v.y + v.z + v.w;
    float ss = v.x * v.x + v.y * v.y + v.z * v.z + v.w * v.w;

#pragma unroll
    for (int off = 16; off > 0; off >>= 1) {
        s  += __shfl_xor_sync(0xffffffffu, s,  off);
        ss += __shfl_xor_sync(0xffffffffu, ss, off);
    }

    __shared__ float sh_s[8], sh_ss[8];
    const int w = tid >> 5, lane = tid & 31;
    if (lane == 0) { sh_s[w] = s; sh_ss[w] = ss; }
    __syncthreads();

    float tot = 0.f, tot2 = 0.f;
#pragma unroll
    for (int i = 0; i < 8; i++) { tot += sh_s[i]; tot2 += sh_ss[i]; }

    const float mean = tot * (1.0f / D_MODEL);
    const float var  = tot2 * (1.0f / D_MODEL) - mean * mean;
    const float rstd = rsqrtf(var + LN_EPS);

    const float4 gg = ((const float4*)gamma)[tid];
    const float4 bb = ((const float4*)beta)[tid];
    float4 rv;
    rv.x = (v.x - mean) * rstd * gg.x + bb.x;
    rv.y = (v.y - mean) * rstd * gg.y + bb.y;
    rv.z = (v.z - mean) * rstd * gg.z + bb.z;
    rv.w = (v.w - mean) * rstd * gg.w + bb.w;
    ((float4*)out)[(size_t)row * (D_MODEL / 4) + tid] = rv;
}

// ---------------------------------------------------------------------------
// Launch
// ---------------------------------------------------------------------------
extern "C" void kernel_launch(void* const* d_in, const int* in_sizes, int n_in,
                              void* d_out, int out_size)
{
    const float* x     = (const float*)d_in[0];
    const float* wq    = (const float*)d_in[1];
    const float* bq    = (const float*)d_in[2];
    const float* wk    = (const float*)d_in[3];
    const float* bk    = (const float*)d_in[4];
    const float* wv    = (const float*)d_in[5];
    const float* bv    = (const float*)d_in[6];
    const float* gamma = (const float*)d_in[7];
    const float* beta  = (const float*)d_in[8];
    float* out = (float*)d_out;

    cudaFuncSetAttribute(attn_mma,
                         cudaFuncAttributeMaxDynamicSharedMemorySize, ATTN_SMEM);

    dim3 ggrid(8, 32, 3);                         // (n-blk, m-blk, {Q,K,V})
    qkv_gemm<<<ggrid, 256>>>(x, wq, bq, wk, bk, wv, bv);

    dim3 agrid(S_LEN / BQ, BATCH * NHEAD);        // (16, 32)
    attn_mma<<<agrid, 256, ATTN_SMEM>>>();

    ln_kernel<<<BATCH * S_LEN, 256>>>(x, gamma, beta, out);
}

// round 3
// speedup vs baseline: 4.6216x; 1.5857x over previous
#include <cuda_runtime.h>
#include <math.h>
#include <stdint.h>

#define BATCH   2
#define S_LEN   2048
#define D_MODEL 1024
#define NHEAD   16
#define HDIM    64
#define LN_EPS  1e-5f

#define BQ      128
#define BKV     128
#define KS_STRIDE 68            // 272B  = 17*16  (cp.async-compatible, conflict-free frags)
#define VS_STRIDE 72            // 288B  = 18*16
#define PS_STRIDE 132           // 528B
#define ATTN_SMEM ((2*BKV*KS_STRIDE + 2*BKV*VS_STRIDE + BQ*PS_STRIDE) * 4)

#define QKV_STAGE_F (128*32*2)              // A + B floats per stage
#define QKV_SMEM    (3 * QKV_STAGE_F * 4)   // 3 stages

// ---------------------------------------------------------------------------
// Scratch (device globals: allocation-free rule). Raw fp32 (HMMA truncates).
// ---------------------------------------------------------------------------
__device__ float g_Q[BATCH * NHEAD * S_LEN * HDIM];
__device__ float g_K[BATCH * NHEAD * S_LEN * HDIM];
__device__ float g_V[BATCH * NHEAD * S_LEN * HDIM];
__device__ float g_O[BATCH * S_LEN * D_MODEL];

// ---------------------------------------------------------------------------
// helpers
// ---------------------------------------------------------------------------
__device__ __forceinline__ void mma8(float c[4], const unsigned a[4],
                                     unsigned b0, unsigned b1) {
    asm volatile(
        "mma.sync.aligned.m16n8k8.row.col.f32.tf32.tf32.f32 "
        "{%0,%1,%2,%3},{%4,%5,%6,%7},{%8,%9},{%0,%1,%2,%3};\n"
        : "+f"(c[0]), "+f"(c[1]), "+f"(c[2]), "+f"(c[3])
        : "r"(a[0]), "r"(a[1]), "r"(a[2]), "r"(a[3]), "r"(b0), "r"(b1));
}

__device__ __forceinline__ void cp16(void* dst, const void* src) {
    unsigned d = (unsigned)__cvta_generic_to_shared(dst);
    asm volatile("cp.async.cg.shared.global [%0], [%1], 16;\n"
                 :: "r"(d), "l"(src));
}
#define CP_COMMIT() asm volatile("cp.async.commit_group;\n" ::: "memory")
#define CP_WAIT(n)  asm volatile("cp.async.wait_group %0;\n" :: "n"(n) : "memory")

// ---------------------------------------------------------------------------
// Fused QKV projection GEMM (tf32 MMA, cp.async 3-stage pipeline).
// Y[m,n] = sum_k X[m,k]*W[n,k] + bias[n]  (Q scaled by 0.125)
// CTA tile 128x128, BK=32, 8 warps (64x32 each). grid=(8,32,3).
// Smem rows: 32 floats, 16B-chunk XOR swizzle (chunk ^= row&7) ->
// conflict-free fragment LDS + aligned cp.async.
// ---------------------------------------------------------------------------
__global__ __launch_bounds__(256, 2)
void qkv_gemm(const float* __restrict__ X,
              const float* __restrict__ Wq, const float* __restrict__ bq,
              const float* __restrict__ Wk, const float* __restrict__ bk,
              const float* __restrict__ Wv, const float* __restrict__ bv)
{
    extern __shared__ float sm[];   // 3 stages: [A 128*32][B 128*32]

    const int z = blockIdx.z;
    const float* W    = (z == 0) ? Wq : (z == 1) ? Wk : Wv;
    const float* bias = (z == 0) ? bq : (z == 1) ? bk : bv;
    float* out        = (z == 0) ? g_Q : (z == 1) ? g_K : g_V;
    const float scale = (z == 0) ? 0.125f : 1.0f;

    const int t    = threadIdx.x;
    const int w    = t >> 5, lane = t & 31;
    const int qh   = lane >> 2, r = lane & 3;
    const int wm   = w >> 2, wn = w & 3;
    const int m0   = blockIdx.y * 128;
    const int n0   = blockIdx.x * 128;

    // loader mapping: 4 float4 per thread per matrix per stage
    const int lrow = t >> 3;            // base row step 32: rows lrow, lrow+32, ...
    const int lch  = t & 7;             // 16B chunk 0..7

    float acc[4][4][4];
#pragma unroll
    for (int i = 0; i < 4; i++)
#pragma unroll
        for (int j = 0; j < 4; j++)
#pragma unroll
            for (int k = 0; k < 4; k++) acc[i][j][k] = 0.0f;

    auto load_stage = [&](int s, int k0) {
        float* As = sm + s * QKV_STAGE_F;
        float* Bs = As + 128 * 32;
#pragma unroll
        for (int i = 0; i < 4; i++) {
            const int row = lrow + i * 32;
            const int dst = row * 32 + ((lch ^ (row & 7)) << 2);
            cp16(As + dst, X + (size_t)(m0 + row) * D_MODEL + k0 + lch * 4);
            cp16(Bs + dst, W + (size_t)(n0 + row) * D_MODEL + k0 + lch * 4);
        }
    };

    load_stage(0, 0);  CP_COMMIT();
    load_stage(1, 32); CP_COMMIT();
    load_stage(2, 64); CP_COMMIT();

    const int NIT = D_MODEL / 32;   // 32
    for (int it = 0; it < NIT; it++) {
        CP_WAIT(2);
        __syncthreads();

        const unsigned* Au = (const unsigned*)(sm + (it % 3) * QKV_STAGE_F);
        const unsigned* Bu = Au + 128 * 32;

#pragma unroll
        for (int kk8 = 0; kk8 < 4; kk8++) {
            const int c0 = (((2 * kk8) ^ qh) << 2) + r;
            const int c1 = (((2 * kk8 + 1) ^ qh) << 2) + r;
            unsigned a[4][4];
#pragma unroll
            for (int i = 0; i < 4; i++) {
                const int rowb = (wm * 64 + 16 * i + qh) * 32;
                a[i][0] = Au[rowb + c0];
                a[i][1] = Au[rowb + 8 * 32 + c0];
                a[i][2] = Au[rowb + c1];
                a[i][3] = Au[rowb + 8 * 32 + c1];
            }
#pragma unroll
            for (int j = 0; j < 4; j++) {
                const int rowb = (wn * 32 + 8 * j + qh) * 32;
                const unsigned b0 = Bu[rowb + c0];
                const unsigned b1 = Bu[rowb + c1];
#pragma unroll
                for (int i = 0; i < 4; i++) mma8(acc[i][j], a[i], b0, b1);
            }
        }
        __syncthreads();

        if (it + 3 < NIT) load_stage(it % 3, (it + 3) * 32);
        CP_COMMIT();
    }

    // Epilogue: +bias, scale, scatter to [B,H,S,hd] (raw fp32)
#pragma unroll
    for (int j = 0; j < 4; j++) {
        const int n = n0 + wn * 32 + 8 * j + 2 * r;
        const float2 bv2 = *(const float2*)(bias + n);
        const int h = n >> 6, hd = n & 63;
#pragma unroll
        for (int i = 0; i < 4; i++) {
            const int m = m0 + wm * 64 + 16 * i + qh;
            {
                const int b = m >> 11, s = m & 2047;
                float* p = out + (((size_t)(b * NHEAD + h) * S_LEN) + s) * HDIM + hd;
                float2 o2;
                o2.x = (acc[i][j][0] + bv2.x) * scale;
                o2.y = (acc[i][j][1] + bv2.y) * scale;
                *(float2*)p = o2;
            }
            {
                const int m2 = m + 8;
                const int b = m2 >> 11, s = m2 & 2047;
                float* p = out + (((size_t)(b * NHEAD + h) * S_LEN) + s) * HDIM + hd;
                float2 o2;
                o2.x = (acc[i][j][2] + bv2.x) * scale;
                o2.y = (acc[i][j][3] + bv2.y) * scale;
                *(float2*)p = o2;
            }
        }
    }
}

// ---------------------------------------------------------------------------
// Flash attention, tf32 MMA, double-buffered K/V via cp.async.
// Grid (16, 32). 256 threads, 8 warps; warp w owns q rows [q0+16w, +16).
// ---------------------------------------------------------------------------
__global__ __launch_bounds__(256, 1)
void attn_mma()
{
    extern __shared__ float sm[];
    float* Kst = sm;                               // 2 x [128*68]
    float* Vst = Kst + 2 * BKV * KS_STRIDE;        // 2 x [128*72]
    float* Ps  = Vst + 2 * BKV * VS_STRIDE;        // [128*132]
    unsigned* Pu = (unsigned*)Ps;

    const int t = threadIdx.x, w = t >> 5, lane = t & 31;
    const int qh = lane >> 2, r = lane & 3;
    const int q0 = blockIdx.x * BQ;
    const int bh = blockIdx.y;

    const float* Kg = g_K + (size_t)bh * S_LEN * HDIM;
    const float* Vg = g_V + (size_t)bh * S_LEN * HDIM;

    auto load_kv = [&](int s, int kv0) {
        float* Ks = Kst + s * BKV * KS_STRIDE;
        float* Vs = Vst + s * BKV * VS_STRIDE;
#pragma unroll
        for (int i = 0; i < 8; i++) {
            const int idx = i * 256 + t;
            const int row = idx >> 4, c4 = (idx & 15) * 4;
            cp16(Ks + row * KS_STRIDE + c4, Kg + (size_t)(kv0 + row) * HDIM + c4);
            cp16(Vs + row * VS_STRIDE + c4, Vg + (size_t)(kv0 + row) * HDIM + c4);
        }
    };

    load_kv(0, 0);   CP_COMMIT();
    load_kv(1, BKV); CP_COMMIT();

    // Q fragments (raw fp32, already scaled by 0.125)
    const float* Qg = g_Q + ((size_t)bh * S_LEN + q0 + 16 * w) * HDIM;
    unsigned qa[8][4];
#pragma unroll
    for (int kd = 0; kd < 8; kd++) {
        qa[kd][0] = __float_as_uint(Qg[qh * 64 + 8 * kd + r]);
        qa[kd][1] = __float_as_uint(Qg[(qh + 8) * 64 + 8 * kd + r]);
        qa[kd][2] = __float_as_uint(Qg[qh * 64 + 8 * kd + r + 4]);
        qa[kd][3] = __float_as_uint(Qg[(qh + 8) * 64 + 8 * kd + r + 4]);
    }

    float o[8][4];
#pragma unroll
    for (int j = 0; j < 8; j++)
#pragma unroll
        for (int k = 0; k < 4; k++) o[j][k] = 0.0f;
    float m0 = -1e30f, m1 = -1e30f, l0 = 0.0f, l1 = 0.0f;

    const int prow0 = (16 * w + qh) * PS_STRIDE;
    const int prow1 = prow0 + 8 * PS_STRIDE;

    const int NT = S_LEN / BKV;    // 16
    for (int it = 0; it < NT; it++) {
        CP_WAIT(1);
        __syncthreads();

        const unsigned* Ku = (const unsigned*)(Kst + (it & 1) * BKV * KS_STRIDE);
        const unsigned* Vu = (const unsigned*)(Vst + (it & 1) * BKV * VS_STRIDE);

        // ---- S = Q @ K^T ----
        float s[16][4];
#pragma unroll
        for (int j = 0; j < 16; j++)
#pragma unroll
            for (int k = 0; k < 4; k++) s[j][k] = 0.0f;

#pragma unroll
        for (int kd = 0; kd < 8; kd++) {
#pragma unroll
            for (int j = 0; j < 16; j++) {
                const int a = (8 * j + qh) * KS_STRIDE + 8 * kd + r;
                mma8(s[j], qa[kd], Ku[a], Ku[a + 4]);
            }
        }

        // ---- online softmax ----
        float mx0 = -1e30f, mx1 = -1e30f;
#pragma unroll
        for (int j = 0; j < 16; j++) {
            mx0 = fmaxf(mx0, fmaxf(s[j][0], s[j][1]));
            mx1 = fmaxf(mx1, fmaxf(s[j][2], s[j][3]));
        }
        mx0 = fmaxf(mx0, __shfl_xor_sync(0xffffffffu, mx0, 1));
        mx0 = fmaxf(mx0, __shfl_xor_sync(0xffffffffu, mx0, 2));
        mx1 = fmaxf(mx1, __shfl_xor_sync(0xffffffffu, mx1, 1));
        mx1 = fmaxf(mx1, __shfl_xor_sync(0xffffffffu, mx1, 2));

        const float n0_ = fmaxf(m0, mx0), n1_ = fmaxf(m1, mx1);
        const float c0 = __expf(m0 - n0_), c1 = __expf(m1 - n1_);
        m0 = n0_; m1 = n1_;

        float rs0 = 0.0f, rs1 = 0.0f;
#pragma unroll
        for (int j = 0; j < 16; j++) {
            s[j][0] = __expf(s[j][0] - m0);
            s[j][1] = __expf(s[j][1] - m0);
            rs0 += s[j][0] + s[j][1];
            s[j][2] = __expf(s[j][2] - m1);
            s[j][3] = __expf(s[j][3] - m1);
            rs1 += s[j][2] + s[j][3];
        }
        rs0 += __shfl_xor_sync(0xffffffffu, rs0, 1);
        rs0 += __shfl_xor_sync(0xffffffffu, rs0, 2);
        rs1 += __shfl_xor_sync(0xffffffffu, rs1, 1);
        rs1 += __shfl_xor_sync(0xffffffffu, rs1, 2);
        l0 = l0 * c0 + rs0;
        l1 = l1 * c1 + rs1;

#pragma unroll
        for (int j = 0; j < 8; j++) {
            o[j][0] *= c0; o[j][1] *= c0;
            o[j][2] *= c1; o[j][3] *= c1;
        }

        // ---- P -> warp-private smem (raw fp32) ----
#pragma unroll
        for (int j = 0; j < 16; j++) {
            *(float2*)&Ps[prow0 + 8 * j + 2 * r] = make_float2(s[j][0], s[j][1]);
            *(float2*)&Ps[prow1 + 8 * j + 2 * r] = make_float2(s[j][2], s[j][3]);
        }
        __syncwarp();

        // ---- O += P @ V ----
#pragma unroll
        for (int kf = 0; kf < 16; kf++) {
            unsigned a[4];
            a[0] = Pu[prow0 + 8 * kf + r];
            a[1] = Pu[prow1 + 8 * kf + r];
            a[2] = Pu[prow0 + 8 * kf + r + 4];
            a[3] = Pu[prow1 + 8 * kf + r + 4];
#pragma unroll
            for (int j = 0; j < 8; j++) {
                const int vb = (8 * kf + r) * VS_STRIDE + 8 * j + qh;
                mma8(o[j], a, Vu[vb], Vu[vb + 4 * VS_STRIDE]);
            }
        }
        __syncthreads();

        if (it + 2 < NT) load_kv(it & 1, (it + 2) * BKV);
        CP_COMMIT();
    }

    // epilogue: O / l -> g_O [B,S,D]
    const float i0 = 1.0f / l0, i1 = 1.0f / l1;
    const int b = bh >> 4, h = bh & 15;
    const int row0 = q0 + 16 * w + qh;
    float* G0 = g_O + ((size_t)b * S_LEN + row0) * D_MODEL + h * HDIM;
    float* G1 = G0 + 8 * D_MODEL;
#pragma unroll
    for (int j = 0; j < 8; j++) {
        const int cc = 8 * j + 2 * r;
        *(float2*)(G0 + cc) = make_float2(o[j][0] * i0, o[j][1] * i0);
        *(float2*)(G1 + cc) = make_float2(o[j][2] * i1, o[j][3] * i1);
    }
}

// ---------------------------------------------------------------------------
// Residual + LayerNorm. Grid: B*S rows, 256 threads (1 float4 each).
// ---------------------------------------------------------------------------
__global__ __launch_bounds__(256)
void ln_kernel(const float* __restrict__ X,
               const float* __restrict__ gamma,
               const float* __restrict__ beta,
               float* __restrict__ out)
{
    const int row = blockIdx.x;
    const int tid = threadIdx.x;

    const float4 a = ((const float4*)(g_O + (size_t)row * D_MODEL))[tid];
    const float4 b = ((const float4*)(X   + (size_t)row * D_MODEL))[tid];
    float4 v;
    v.x = a.x + b.x; v.y = a.y + b.y; v.z = a.z + b.z; v.w = a.w + b.w;

    float s  = v.x + v.y + v.z + v.w;
    float ss = v.x * v.x + v.y * v.y + v.z * v.z + v.w * v.w;

#pragma unroll
    for (int off = 16; off > 0; off >>= 1) {
        s  += __shfl_xor_sync(0xffffffffu, s,  off);
        ss += __shfl_xor_sync(0xffffffffu, ss, off);
    }

    __shared__ float sh_s[8], sh_ss[8];
    const int w = tid >> 5, lane = tid & 31;
    if (lane == 0) { sh_s[w] = s; sh_ss[w] = ss; }
    __syncthreads();

    float tot = 0.f, tot2 = 0.f;
#pragma unroll
    for (int i = 0; i < 8; i++) { tot += sh_s[i]; tot2 += sh_ss[i]; }

    const float mean = tot * (1.0f / D_MODEL);
    const float var  = tot2 * (1.0f / D_MODEL) - mean * mean;
    const float rstd = rsqrtf(var + LN_EPS);

    const float4 gg = ((const float4*)gamma)[tid];
    const float4 bb = ((const float4*)beta)[tid];
    float4 rv;
    rv.x = (v.x - mean) * rstd * gg.x + bb.x;
    rv.y = (v.y - mean) * rstd * gg.y + bb.y;
    rv.z = (v.z - mean) * rstd * gg.z + bb.z;
    rv.w = (v.w - mean) * rstd * gg.w + bb.w;
    ((float4*)out)[(size_t)row * (D_MODEL / 4) + tid] = rv;
}

// ---------------------------------------------------------------------------
// Launch
// ---------------------------------------------------------------------------
extern "C" void kernel_launch(void* const* d_in, const int* in_sizes, int n_in,
                              void* d_out, int out_size)
{
    const float* x     = (const float*)d_in[0];
    const float* wq    = (const float*)d_in[1];
    const float* bq    = (const float*)d_in[2];
    const float* wk    = (const float*)d_in[3];
    const float* bk    = (const float*)d_in[4];
    const float* wv    = (const float*)d_in[5];
    const float* bv    = (const float*)d_in[6];
    const float* gamma = (const float*)d_in[7];
    const float* beta  = (const float*)d_in[8];
    float* out = (float*)d_out;

    static bool attrs_set = false;
    if (!attrs_set) {
        cudaFuncSetAttribute(qkv_gemm,
                             cudaFuncAttributeMaxDynamicSharedMemorySize, QKV_SMEM);
        cudaFuncSetAttribute(attn_mma,
                             cudaFuncAttributeMaxDynamicSharedMemorySize, ATTN_SMEM);
        attrs_set = true;
    }

    dim3 ggrid(8, 32, 3);
    qkv_gemm<<<ggrid, 256, QKV_SMEM>>>(x, wq, bq, wk, bk, wv, bv);

    dim3 agrid(S_LEN / BQ, BATCH * NHEAD);
    attn_mma<<<agrid, 256, ATTN_SMEM>>>();

    ln_kernel<<<BATCH * S_LEN, 256>>>(x, gamma, beta, out);
}

// round 4
// speedup vs baseline: 7.0621x; 1.5280x over previous
#include <cuda_runtime.h>
#include <cuda_bf16.h>
#include <math.h>
#include <stdint.h>

#define BATCH   2
#define S_LEN   2048
#define D_MODEL 1024
#define NHEAD   16
#define HDIM    64
#define LN_EPS  1e-5f

#define BQ      128
#define BKV     128

// attention smem strides (uints)
#define KT_STRIDE 36     // 128 bf16 row -> 32 uints + 4 pad (144B, 16B-mult)
#define VT_STRIDE 68     // 128 bf16 row -> 64 uints + 4 pad (272B)
#define PT_STRIDE 68
#define ATTN_SMEM ((2*BKV*KT_STRIDE + 2*HDIM*VT_STRIDE + BQ*PT_STRIDE) * 4)

// qkv gemm smem
#define QKV_ROWU   20                       // 32 bf16 -> 16 uints + 4 pad (80B)
#define QKV_STAGE_U (128*QKV_ROWU*2)        // A + B
#define QKV_SMEM   (3 * QKV_STAGE_U * 4)

#define XN (BATCH*S_LEN*D_MODEL)
#define WN (D_MODEL*D_MODEL)

// ---------------------------------------------------------------------------
// Scratch (device globals)
// ---------------------------------------------------------------------------
__device__ __nv_bfloat16 g_Xb[XN];
__device__ __nv_bfloat16 g_Wqb[WN];
__device__ __nv_bfloat16 g_Wkb[WN];
__device__ __nv_bfloat16 g_Wvb[WN];
__device__ __nv_bfloat16 g_Q [BATCH * NHEAD * S_LEN * HDIM];   // [B,H,S,hd]
__device__ __nv_bfloat16 g_K [BATCH * NHEAD * S_LEN * HDIM];   // [B,H,S,hd]
__device__ __nv_bfloat16 g_Vt[BATCH * NHEAD * HDIM * S_LEN];   // [B,H,hd,S]
__device__ float         g_O [BATCH * S_LEN * D_MODEL];

// ---------------------------------------------------------------------------
// helpers
// ---------------------------------------------------------------------------
__device__ __forceinline__ unsigned packbf(float lo, float hi) {
    unsigned d;
    asm("cvt.rn.bf16x2.f32 %0, %1, %2;" : "=r"(d) : "f"(hi), "f"(lo));
    return d;
}

__device__ __forceinline__ void mma16(float c[4], const unsigned a[4],
                                      unsigned b0, unsigned b1) {
    asm volatile(
        "mma.sync.aligned.m16n8k16.row.col.f32.bf16.bf16.f32 "
        "{%0,%1,%2,%3},{%4,%5,%6,%7},{%8,%9},{%0,%1,%2,%3};\n"
        : "+f"(c[0]), "+f"(c[1]), "+f"(c[2]), "+f"(c[3])
        : "r"(a[0]), "r"(a[1]), "r"(a[2]), "r"(a[3]), "r"(b0), "r"(b1));
}

__device__ __forceinline__ void cp16(void* dst, const void* src) {
    unsigned d = (unsigned)__cvta_generic_to_shared(dst);
    asm volatile("cp.async.cg.shared.global [%0], [%1], 16;\n"
                 :: "r"(d), "l"(src));
}
#define CP_COMMIT() asm volatile("cp.async.commit_group;\n" ::: "memory")
#define CP_WAIT(n)  asm volatile("cp.async.wait_group %0;\n" :: "n"(n) : "memory")

// ---------------------------------------------------------------------------
// fp32 -> bf16 conversion of X, Wq, Wk, Wv (one shot, ~42MB traffic)
// ---------------------------------------------------------------------------
__global__ __launch_bounds__(256)
void cvt_kernel(const float* __restrict__ x,  const float* __restrict__ wq,
                const float* __restrict__ wk, const float* __restrict__ wv)
{
    const size_t i4 = ((size_t)blockIdx.x * 256 + threadIdx.x) * 4;
    const float* src; __nv_bfloat16* dst; size_t off;
    if      (i4 < XN)          { src = x;  dst = g_Xb;  off = i4; }
    else if (i4 < XN + WN)     { src = wq; dst = g_Wqb; off = i4 - XN; }
    else if (i4 < XN + 2 * WN) { src = wk; dst = g_Wkb; off = i4 - XN - WN; }
    else                       { src = wv; dst = g_Wvb; off = i4 - XN - 2 * WN; }
    const float4 v = *(const float4*)(src + off);
    uint2 u;
    u.x = packbf(v.x, v.y);
    u.y = packbf(v.z, v.w);
    *(uint2*)(dst + off) = u;
}

// ---------------------------------------------------------------------------
// Fused QKV projection GEMM, bf16 MMA (m16n8k16), cp.async 3-stage pipeline.
// Y[m,n] = sum_k X[m,k]*W[n,k] + bias[n]  (Q scaled by 0.125)
// CTA tile 128x128, BK=32, 8 warps (64x32 each). grid=(8,32,3).
// Q/K written bf16 packed [B,H,S,hd]; V written bf16 transposed [B,H,hd,S].
// ---------------------------------------------------------------------------
__global__ __launch_bounds__(256, 2)
void qkv_gemm(const float* __restrict__ bq,
              const float* __restrict__ bk,
              const float* __restrict__ bv)
{
    extern __shared__ unsigned smu[];   // 3 stages: [A 128*20][B 128*20]

    const int z = blockIdx.z;
    const __nv_bfloat16* W = (z == 0) ? g_Wqb : (z == 1) ? g_Wkb : g_Wvb;
    const float* bias      = (z == 0) ? bq : (z == 1) ? bk : bv;
    const float scale      = (z == 0) ? 0.125f : 1.0f;

    const int t    = threadIdx.x;
    const int w    = t >> 5, lane = t & 31;
    const int qh   = lane >> 2, r = lane & 3;
    const int wm   = w >> 2, wn = w & 3;
    const int m0   = blockIdx.y * 128;
    const int n0   = blockIdx.x * 128;

    float acc[4][4][4];
#pragma unroll
    for (int i = 0; i < 4; i++)
#pragma unroll
        for (int j = 0; j < 4; j++)
#pragma unroll
            for (int k = 0; k < 4; k++) acc[i][j][k] = 0.0f;

    auto load_stage = [&](int s, int k0) {
        unsigned* As = smu + s * QKV_STAGE_U;
        unsigned* Bs = As + 128 * QKV_ROWU;
#pragma unroll
        for (int i = 0; i < 2; i++) {
            const int idx = i * 256 + t;
            const int row = idx >> 2, ch = idx & 3;
            cp16(As + row * QKV_ROWU + ch * 4,
                 g_Xb + (size_t)(m0 + row) * D_MODEL + k0 + ch * 8);
            cp16(Bs + row * QKV_ROWU + ch * 4,
                 W + (size_t)(n0 + row) * D_MODEL + k0 + ch * 8);
        }
    };

    load_stage(0, 0);  CP_COMMIT();
    load_stage(1, 32); CP_COMMIT();
    load_stage(2, 64); CP_COMMIT();

    const int NIT = D_MODEL / 32;   // 32
    for (int it = 0; it < NIT; it++) {
        CP_WAIT(2);
        __syncthreads();

        const unsigned* Au = smu + (it % 3) * QKV_STAGE_U;
        const unsigned* Bu = Au + 128 * QKV_ROWU;

#pragma unroll
        for (int kk = 0; kk < 2; kk++) {
            const int cb = kk * 8 + r;
            unsigned a[4][4];
#pragma unroll
            for (int i = 0; i < 4; i++) {
                const int rowb = (wm * 64 + 16 * i + qh) * QKV_ROWU;
                a[i][0] = Au[rowb + cb];
                a[i][1] = Au[rowb + 8 * QKV_ROWU + cb];
                a[i][2] = Au[rowb + cb + 4];
                a[i][3] = Au[rowb + 8 * QKV_ROWU + cb + 4];
            }
#pragma unroll
            for (int j = 0; j < 4; j++) {
                const int rowb = (wn * 32 + 8 * j + qh) * QKV_ROWU;
                const unsigned b0 = Bu[rowb + cb];
                const unsigned b1 = Bu[rowb + cb + 4];
#pragma unroll
                for (int i = 0; i < 4; i++) mma16(acc[i][j], a[i], b0, b1);
            }
        }
        __syncthreads();

        if (it + 3 < NIT) load_stage(it % 3, (it + 3) * 32);
        CP_COMMIT();
    }

    // Epilogue
#pragma unroll
    for (int j = 0; j < 4; j++) {
        const int n = n0 + wn * 32 + 8 * j + 2 * r;
        const float2 bv2 = *(const float2*)(bias + n);
        const int h = n >> 6, hd = n & 63;
#pragma unroll
        for (int i = 0; i < 4; i++) {
            const int m = m0 + wm * 64 + 16 * i + qh;
            const int b = m >> 11, s = m & 2047;
            const float v0 = (acc[i][j][0] + bv2.x) * scale;
            const float v1 = (acc[i][j][1] + bv2.y) * scale;
            const float v2 = (acc[i][j][2] + bv2.x) * scale;
            const float v3 = (acc[i][j][3] + bv2.y) * scale;
            if (z < 2) {
                __nv_bfloat16* out = (z == 0) ? g_Q : g_K;
                unsigned* ou = (unsigned*)out;
                const size_t base = (((size_t)(b * NHEAD + h) * S_LEN)) * 32;
                ou[base + (size_t)s * 32 + (hd >> 1)]       = packbf(v0, v1);
                ou[base + (size_t)(s + 8) * 32 + (hd >> 1)] = packbf(v2, v3);
            } else {
                __nv_bfloat16* vt = g_Vt
                    + ((size_t)(b * NHEAD + h) * HDIM) * S_LEN;
                vt[(size_t)hd * S_LEN + s]           = __float2bfloat16_rn(v0);
                vt[(size_t)(hd + 1) * S_LEN + s]     = __float2bfloat16_rn(v1);
                vt[(size_t)hd * S_LEN + s + 8]       = __float2bfloat16_rn(v2);
                vt[(size_t)(hd + 1) * S_LEN + s + 8] = __float2bfloat16_rn(v3);
            }
        }
    }
}

// ---------------------------------------------------------------------------
// Flash attention, bf16 MMA, double-buffered K / Vt via cp.async.
// Grid (16, 32). 256 threads, 8 warps; warp w owns q rows [q0+16w, +16).
// ---------------------------------------------------------------------------
__global__ __launch_bounds__(256, 2)
void attn_mma()
{
    extern __shared__ unsigned smu[];
    unsigned* Kst = smu;                                 // 2 x [128*36]
    unsigned* Vst = Kst + 2 * BKV * KT_STRIDE;           // 2 x [64*68]
    unsigned* Pu  = Vst + 2 * HDIM * VT_STRIDE;          // [128*68]

    const int t = threadIdx.x, w = t >> 5, lane = t & 31;
    const int qh = lane >> 2, r = lane & 3;
    const int q0 = blockIdx.x * BQ;
    const int bh = blockIdx.y;

    const __nv_bfloat16* Kg  = g_K  + (size_t)bh * S_LEN * HDIM;
    const __nv_bfloat16* Vtg = g_Vt + (size_t)bh * HDIM * S_LEN;

    auto load_kv = [&](int s, int kv0) {
        unsigned* Ks = Kst + s * BKV * KT_STRIDE;
        unsigned* Vs = Vst + s * HDIM * VT_STRIDE;
#pragma unroll
        for (int i = 0; i < 4; i++) {
            const int idx = i * 256 + t;
            {   // K: 128 rows x 8 chunks
                const int row = idx >> 3, ch = idx & 7;
                cp16(Ks + row * KT_STRIDE + ch * 4,
                     Kg + (size_t)(kv0 + row) * HDIM + ch * 8);
            }
            {   // Vt: 64 rows x 16 chunks
                const int row = idx >> 4, ch = idx & 15;
                cp16(Vs + row * VT_STRIDE + ch * 4,
                     Vtg + (size_t)row * S_LEN + kv0 + ch * 8);
            }
        }
    };

    load_kv(0, 0);   CP_COMMIT();
    load_kv(1, BKV); CP_COMMIT();

    // Q fragments (bf16 packed, pre-scaled by 0.125)
    const unsigned* Qu = (const unsigned*)
        (g_Q + ((size_t)bh * S_LEN + q0 + 16 * w) * HDIM);
    unsigned qa[4][4];
#pragma unroll
    for (int kd = 0; kd < 4; kd++) {
        qa[kd][0] = Qu[qh * 32 + kd * 8 + r];
        qa[kd][1] = Qu[(qh + 8) * 32 + kd * 8 + r];
        qa[kd][2] = Qu[qh * 32 + kd * 8 + r + 4];
        qa[kd][3] = Qu[(qh + 8) * 32 + kd * 8 + r + 4];
    }

    float o[8][4];
#pragma unroll
    for (int j = 0; j < 8; j++)
#pragma unroll
        for (int k = 0; k < 4; k++) o[j][k] = 0.0f;
    float m0 = -1e30f, m1 = -1e30f, l0 = 0.0f, l1 = 0.0f;

    const int prow0 = (16 * w + qh) * PT_STRIDE;
    const int prow1 = prow0 + 8 * PT_STRIDE;

    const int NT = S_LEN / BKV;    // 16
    for (int it = 0; it < NT; it++) {
        CP_WAIT(1);
        __syncthreads();

        const unsigned* Ku  = Kst + (it & 1) * BKV * KT_STRIDE;
        const unsigned* Vtu = Vst + (it & 1) * HDIM * VT_STRIDE;

        // ---- S = Q @ K^T ----
        float s[16][4];
#pragma unroll
        for (int j = 0; j < 16; j++)
#pragma unroll
            for (int k = 0; k < 4; k++) s[j][k] = 0.0f;

#pragma unroll
        for (int kd = 0; kd < 4; kd++) {
#pragma unroll
            for (int j = 0; j < 16; j++) {
                const int a = (8 * j + qh) * KT_STRIDE + kd * 8 + r;
                mma16(s[j], qa[kd], Ku[a], Ku[a + 4]);
            }
        }

        // ---- online softmax ----
        float mx0 = -1e30f, mx1 = -1e30f;
#pragma unroll
        for (int j = 0; j < 16; j++) {
            mx0 = fmaxf(mx0, fmaxf(s[j][0], s[j][1]));
            mx1 = fmaxf(mx1, fmaxf(s[j][2], s[j][3]));
        }
        mx0 = fmaxf(mx0, __shfl_xor_sync(0xffffffffu, mx0, 1));
        mx0 = fmaxf(mx0, __shfl_xor_sync(0xffffffffu, mx0, 2));
        mx1 = fmaxf(mx1, __shfl_xor_sync(0xffffffffu, mx1, 1));
        mx1 = fmaxf(mx1, __shfl_xor_sync(0xffffffffu, mx1, 2));

        const float n0_ = fmaxf(m0, mx0), n1_ = fmaxf(m1, mx1);
        const float c0 = __expf(m0 - n0_), c1 = __expf(m1 - n1_);
        m0 = n0_; m1 = n1_;

        float rs0 = 0.0f, rs1 = 0.0f;
#pragma unroll
        for (int j = 0; j < 16; j++) {
            s[j][0] = __expf(s[j][0] - m0);
            s[j][1] = __expf(s[j][1] - m0);
            rs0 += s[j][0] + s[j][1];
            s[j][2] = __expf(s[j][2] - m1);
            s[j][3] = __expf(s[j][3] - m1);
            rs1 += s[j][2] + s[j][3];
        }
        rs0 += __shfl_xor_sync(0xffffffffu, rs0, 1);
        rs0 += __shfl_xor_sync(0xffffffffu, rs0, 2);
        rs1 += __shfl_xor_sync(0xffffffffu, rs1, 1);
        rs1 += __shfl_xor_sync(0xffffffffu, rs1, 2);
        l0 = l0 * c0 + rs0;
        l1 = l1 * c1 + rs1;

#pragma unroll
        for (int j = 0; j < 8; j++) {
            o[j][0] *= c0; o[j][1] *= c0;
            o[j][2] *= c1; o[j][3] *= c1;
        }

        // ---- P -> warp-private smem (bf16 packed) ----
#pragma unroll
        for (int j = 0; j < 16; j++) {
            Pu[prow0 + 4 * j + r] = packbf(s[j][0], s[j][1]);
            Pu[prow1 + 4 * j + r] = packbf(s[j][2], s[j][3]);
        }
        __syncwarp();

        // ---- O += P @ V ----
#pragma unroll
        for (int kf = 0; kf < 8; kf++) {
            unsigned a[4];
            a[0] = Pu[prow0 + kf * 8 + r];
            a[1] = Pu[prow1 + kf * 8 + r];
            a[2] = Pu[prow0 + kf * 8 + r + 4];
            a[3] = Pu[prow1 + kf * 8 + r + 4];
#pragma unroll
            for (int j = 0; j < 8; j++) {
                const int vb = (8 * j + qh) * VT_STRIDE + kf * 8 + r;
                mma16(o[j], a, Vtu[vb], Vtu[vb + 4]);
            }
        }
        __syncthreads();

        if (it + 2 < NT) load_kv(it & 1, (it + 2) * BKV);
        CP_COMMIT();
    }

    // epilogue: O / l -> g_O [B,S,D] (fp32)
    const float i0 = 1.0f / l0, i1 = 1.0f / l1;
    const int b = bh >> 4, h = bh & 15;
    const int row0 = q0 + 16 * w + qh;
    float* G0 = g_O + ((size_t)b * S_LEN + row0) * D_MODEL + h * HDIM;
    float* G1 = G0 + 8 * D_MODEL;
#pragma unroll
    for (int j = 0; j < 8; j++) {
        const int cc = 8 * j + 2 * r;
        *(float2*)(G0 + cc) = make_float2(o[j][0] * i0, o[j][1] * i0);
        *(float2*)(G1 + cc) = make_float2(o[j][2] * i1, o[j][3] * i1);
    }
}

// ---------------------------------------------------------------------------
// Residual + LayerNorm. Grid: B*S rows, 256 threads (1 float4 each).
// ---------------------------------------------------------------------------
__global__ __launch_bounds__(256)
void ln_kernel(const float* __restrict__ X,
               const float* __restrict__ gamma,
               const float* __restrict__ beta,
               float* __restrict__ out)
{
    const int row = blockIdx.x;
    const int tid = threadIdx.x;

    const float4 a = ((const float4*)(g_O + (size_t)row * D_MODEL))[tid];
    const float4 b = ((const float4*)(X   + (size_t)row * D_MODEL))[tid];
    float4 v;
    v.x = a.x + b.x; v.y = a.y + b.y; v.z = a.z + b.z; v.w = a.w + b.w;

    float s  = v.x + v.y + v.z + v.w;
    float ss = v.x * v.x + v.y * v.y + v.z * v.z + v.w * v.w;

#pragma unroll
    for (int off = 16; off > 0; off >>= 1) {
        s  += __shfl_xor_sync(0xffffffffu, s,  off);
        ss += __shfl_xor_sync(0xffffffffu, ss, off);
    }

    __shared__ float sh_s[8], sh_ss[8];
    const int w = tid >> 5, lane = tid & 31;
    if (lane == 0) { sh_s[w] = s; sh_ss[w] = ss; }
    __syncthreads();

    float tot = 0.f, tot2 = 0.f;
#pragma unroll
    for (int i = 0; i < 8; i++) { tot += sh_s[i]; tot2 += sh_ss[i]; }

    const float mean = tot * (1.0f / D_MODEL);
    const float var  = tot2 * (1.0f / D_MODEL) - mean * mean;
    const float rstd = rsqrtf(var + LN_EPS);

    const float4 gg = ((const float4*)gamma)[tid];
    const float4 bb = ((const float4*)beta)[tid];
    float4 rv;
    rv.x = (v.x - mean) * rstd * gg.x + bb.x;
    rv.y = (v.y - mean) * rstd * gg.y + bb.y;
    rv.z = (v.z - mean) * rstd * gg.z + bb.z;
    rv.w = (v.w - mean) * rstd * gg.w + bb.w;
    ((float4*)out)[(size_t)row * (D_MODEL / 4) + tid] = rv;
}

// ---------------------------------------------------------------------------
// Launch
// ---------------------------------------------------------------------------
extern "C" void kernel_launch(void* const* d_in, const int* in_sizes, int n_in,
                              void* d_out, int out_size)
{
    const float* x     = (const float*)d_in[0];
    const float* wq    = (const float*)d_in[1];
    const float* bq    = (const float*)d_in[2];
    const float* wk    = (const float*)d_in[3];
    const float* bk    = (const float*)d_in[4];
    const float* wv    = (const float*)d_in[5];
    const float* bv    = (const float*)d_in[6];
    const float* gamma = (const float*)d_in[7];
    const float* beta  = (const float*)d_in[8];
    float* out = (float*)d_out;

    static bool attrs_set = false;
    if (!attrs_set) {
        cudaFuncSetAttribute(qkv_gemm,
                             cudaFuncAttributeMaxDynamicSharedMemorySize, QKV_SMEM);
        cudaFuncSetAttribute(attn_mma,
                             cudaFuncAttributeMaxDynamicSharedMemorySize, ATTN_SMEM);
        attrs_set = true;
    }

    const int ntot = XN + 3 * WN;
    cvt_kernel<<<ntot / (256 * 4), 256>>>(x, wq, wk, wv);

    dim3 ggrid(8, 32, 3);
    qkv_gemm<<<ggrid, 256, QKV_SMEM>>>(bq, bk, bv);

    dim3 agrid(S_LEN / BQ, BATCH * NHEAD);
    attn_mma<<<agrid, 256, ATTN_SMEM>>>();

    ln_kernel<<<BATCH * S_LEN, 256>>>(x, gamma, beta, out);
}

// round 5
// speedup vs baseline: 7.0843x; 1.0032x over previous
#include <cuda_runtime.h>
#include <cuda_bf16.h>
#include <math.h>
#include <stdint.h>

#define BATCH   2
#define S_LEN   2048
#define D_MODEL 1024
#define NHEAD   16
#define HDIM    64
#define LN_EPS  1e-5f

#define BQ      128
#define BKV     128

// attention smem strides (uints)
#define KT_STRIDE 36     // 128 bf16 row -> 32 uints + 4 pad (144B, 16B-mult)
#define VT_STRIDE 68     // 128 bf16 row -> 64 uints + 4 pad (272B)
#define PT_STRIDE 68
#define ATTN_SMEM ((2*BKV*KT_STRIDE + 2*HDIM*VT_STRIDE + BQ*PT_STRIDE) * 4)

// qkv gemm smem
#define QKV_ROWU   20                       // 32 bf16 -> 16 uints + 4 pad (80B)
#define QKV_STAGE_U (128*QKV_ROWU*2)        // A + B
#define QKV_SMEM   (3 * QKV_STAGE_U * 4)

#define XN (BATCH*S_LEN*D_MODEL)
#define WN (D_MODEL*D_MODEL)

// ---------------------------------------------------------------------------
// Scratch (device globals)
// ---------------------------------------------------------------------------
__device__ __nv_bfloat16 g_Xb[XN];
__device__ __nv_bfloat16 g_Wqb[WN];
__device__ __nv_bfloat16 g_Wkb[WN];
__device__ __nv_bfloat16 g_Wvb[WN];
__device__ __nv_bfloat16 g_Q [BATCH * NHEAD * S_LEN * HDIM];   // [B,H,S,hd]
__device__ __nv_bfloat16 g_K [BATCH * NHEAD * S_LEN * HDIM];   // [B,H,S,hd]
__device__ __nv_bfloat16 g_Vt[BATCH * NHEAD * HDIM * S_LEN];   // [B,H,hd,S]
__device__ float         g_O [BATCH * S_LEN * D_MODEL];

// ---------------------------------------------------------------------------
// helpers
// ---------------------------------------------------------------------------
__device__ __forceinline__ unsigned packbf(float lo, float hi) {
    unsigned d;
    asm("cvt.rn.bf16x2.f32 %0, %1, %2;" : "=r"(d) : "f"(hi), "f"(lo));
    return d;
}

__device__ __forceinline__ void mma16(float c[4], const unsigned a[4],
                                      unsigned b0, unsigned b1) {
    asm volatile(
        "mma.sync.aligned.m16n8k16.row.col.f32.bf16.bf16.f32 "
        "{%0,%1,%2,%3},{%4,%5,%6,%7},{%8,%9},{%0,%1,%2,%3};\n"
        : "+f"(c[0]), "+f"(c[1]), "+f"(c[2]), "+f"(c[3])
        : "r"(a[0]), "r"(a[1]), "r"(a[2]), "r"(a[3]), "r"(b0), "r"(b1));
}

__device__ __forceinline__ void cp16(void* dst, const void* src) {
    unsigned d = (unsigned)__cvta_generic_to_shared(dst);
    asm volatile("cp.async.cg.shared.global [%0], [%1], 16;\n"
                 :: "r"(d), "l"(src));
}
#define CP_COMMIT() asm volatile("cp.async.commit_group;\n" ::: "memory")
#define CP_WAIT(n)  asm volatile("cp.async.wait_group %0;\n" :: "n"(n) : "memory")

// ---------------------------------------------------------------------------
// fp32 -> bf16 conversion of X, Wq, Wk, Wv (one shot, ~42MB traffic)
// ---------------------------------------------------------------------------
__global__ __launch_bounds__(256)
void cvt_kernel(const float* __restrict__ x,  const float* __restrict__ wq,
                const float* __restrict__ wk, const float* __restrict__ wv)
{
    const size_t i4 = ((size_t)blockIdx.x * 256 + threadIdx.x) * 4;
    const float* src; __nv_bfloat16* dst; size_t off;
    if      (i4 < XN)          { src = x;  dst = g_Xb;  off = i4; }
    else if (i4 < XN + WN)     { src = wq; dst = g_Wqb; off = i4 - XN; }
    else if (i4 < XN + 2 * WN) { src = wk; dst = g_Wkb; off = i4 - XN - WN; }
    else                       { src = wv; dst = g_Wvb; off = i4 - XN - 2 * WN; }
    const float4 v = *(const float4*)(src + off);
    uint2 u;
    u.x = packbf(v.x, v.y);
    u.y = packbf(v.z, v.w);
    *(uint2*)(dst + off) = u;
}

// ---------------------------------------------------------------------------
// Fused QKV projection GEMM, bf16 MMA (m16n8k16), cp.async 3-stage pipeline.
// Y[m,n] = sum_k X[m,k]*W[n,k] + bias[n]  (Q scaled by 0.125)
// CTA tile 128x128, BK=32, 8 warps (64x32 each). grid=(8,32,3).
// Q/K written bf16 packed [B,H,S,hd]; V written bf16 transposed [B,H,hd,S].
// ---------------------------------------------------------------------------
__global__ __launch_bounds__(256, 2)
void qkv_gemm(const float* __restrict__ bq,
              const float* __restrict__ bk,
              const float* __restrict__ bv)
{
    extern __shared__ unsigned smu[];   // 3 stages: [A 128*20][B 128*20]

    const int z = blockIdx.z;
    const __nv_bfloat16* W = (z == 0) ? g_Wqb : (z == 1) ? g_Wkb : g_Wvb;
    const float* bias      = (z == 0) ? bq : (z == 1) ? bk : bv;
    const float scale      = (z == 0) ? 0.125f : 1.0f;

    const int t    = threadIdx.x;
    const int w    = t >> 5, lane = t & 31;
    const int qh   = lane >> 2, r = lane & 3;
    const int wm   = w >> 2, wn = w & 3;
    const int m0   = blockIdx.y * 128;
    const int n0   = blockIdx.x * 128;

    float acc[4][4][4];
#pragma unroll
    for (int i = 0; i < 4; i++)
#pragma unroll
        for (int j = 0; j < 4; j++)
#pragma unroll
            for (int k = 0; k < 4; k++) acc[i][j][k] = 0.0f;

    auto load_stage = [&](int s, int k0) {
        unsigned* As = smu + s * QKV_STAGE_U;
        unsigned* Bs = As + 128 * QKV_ROWU;
#pragma unroll
        for (int i = 0; i < 2; i++) {
            const int idx = i * 256 + t;
            const int row = idx >> 2, ch = idx & 3;
            cp16(As + row * QKV_ROWU + ch * 4,
                 g_Xb + (size_t)(m0 + row) * D_MODEL + k0 + ch * 8);
            cp16(Bs + row * QKV_ROWU + ch * 4,
                 W + (size_t)(n0 + row) * D_MODEL + k0 + ch * 8);
        }
    };

    load_stage(0, 0);  CP_COMMIT();
    load_stage(1, 32); CP_COMMIT();
    load_stage(2, 64); CP_COMMIT();

    const int NIT = D_MODEL / 32;   // 32
    for (int it = 0; it < NIT; it++) {
        CP_WAIT(2);
        __syncthreads();

        const unsigned* Au = smu + (it % 3) * QKV_STAGE_U;
        const unsigned* Bu = Au + 128 * QKV_ROWU;

#pragma unroll
        for (int kk = 0; kk < 2; kk++) {
            const int cb = kk * 8 + r;
            unsigned a[4][4];
#pragma unroll
            for (int i = 0; i < 4; i++) {
                const int rowb = (wm * 64 + 16 * i + qh) * QKV_ROWU;
                a[i][0] = Au[rowb + cb];
                a[i][1] = Au[rowb + 8 * QKV_ROWU + cb];
                a[i][2] = Au[rowb + cb + 4];
                a[i][3] = Au[rowb + 8 * QKV_ROWU + cb + 4];
            }
#pragma unroll
            for (int j = 0; j < 4; j++) {
                const int rowb = (wn * 32 + 8 * j + qh) * QKV_ROWU;
                const unsigned b0 = Bu[rowb + cb];
                const unsigned b1 = Bu[rowb + cb + 4];
#pragma unroll
                for (int i = 0; i < 4; i++) mma16(acc[i][j], a[i], b0, b1);
            }
        }
        __syncthreads();

        if (it + 3 < NIT) load_stage(it % 3, (it + 3) * 32);
        CP_COMMIT();
    }

    // Epilogue
#pragma unroll
    for (int j = 0; j < 4; j++) {
        const int n = n0 + wn * 32 + 8 * j + 2 * r;
        const float2 bv2 = *(const float2*)(bias + n);
        const int h = n >> 6, hd = n & 63;
#pragma unroll
        for (int i = 0; i < 4; i++) {
            const int m = m0 + wm * 64 + 16 * i + qh;
            const int b = m >> 11, s = m & 2047;
            const float v0 = (acc[i][j][0] + bv2.x) * scale;
            const float v1 = (acc[i][j][1] + bv2.y) * scale;
            const float v2 = (acc[i][j][2] + bv2.x) * scale;
            const float v3 = (acc[i][j][3] + bv2.y) * scale;
            if (z < 2) {
                __nv_bfloat16* out = (z == 0) ? g_Q : g_K;
                unsigned* ou = (unsigned*)out;
                const size_t base = (((size_t)(b * NHEAD + h) * S_LEN)) * 32;
                ou[base + (size_t)s * 32 + (hd >> 1)]       = packbf(v0, v1);
                ou[base + (size_t)(s + 8) * 32 + (hd >> 1)] = packbf(v2, v3);
            } else {
                __nv_bfloat16* vt = g_Vt
                    + ((size_t)(b * NHEAD + h) * HDIM) * S_LEN;
                vt[(size_t)hd * S_LEN + s]           = __float2bfloat16_rn(v0);
                vt[(size_t)(hd + 1) * S_LEN + s]     = __float2bfloat16_rn(v1);
                vt[(size_t)hd * S_LEN + s + 8]       = __float2bfloat16_rn(v2);
                vt[(size_t)(hd + 1) * S_LEN + s + 8] = __float2bfloat16_rn(v3);
            }
        }
    }
}

// ---------------------------------------------------------------------------
// Flash attention, bf16 MMA, double-buffered K / Vt via cp.async.
// Grid (16, 32). 256 threads, 8 warps; warp w owns q rows [q0+16w, +16).
// ---------------------------------------------------------------------------
__global__ __launch_bounds__(256, 2)
void attn_mma()
{
    extern __shared__ unsigned smu[];
    unsigned* Kst = smu;                                 // 2 x [128*36]
    unsigned* Vst = Kst + 2 * BKV * KT_STRIDE;           // 2 x [64*68]
    unsigned* Pu  = Vst + 2 * HDIM * VT_STRIDE;          // [128*68]

    const int t = threadIdx.x, w = t >> 5, lane = t & 31;
    const int qh = lane >> 2, r = lane & 3;
    const int q0 = blockIdx.x * BQ;
    const int bh = blockIdx.y;

    const __nv_bfloat16* Kg  = g_K  + (size_t)bh * S_LEN * HDIM;
    const __nv_bfloat16* Vtg = g_Vt + (size_t)bh * HDIM * S_LEN;

    auto load_kv = [&](int s, int kv0) {
        unsigned* Ks = Kst + s * BKV * KT_STRIDE;
        unsigned* Vs = Vst + s * HDIM * VT_STRIDE;
#pragma unroll
        for (int i = 0; i < 4; i++) {
            const int idx = i * 256 + t;
            {   // K: 128 rows x 8 chunks
                const int row = idx >> 3, ch = idx & 7;
                cp16(Ks + row * KT_STRIDE + ch * 4,
                     Kg + (size_t)(kv0 + row) * HDIM + ch * 8);
            }
            {   // Vt: 64 rows x 16 chunks
                const int row = idx >> 4, ch = idx & 15;
                cp16(Vs + row * VT_STRIDE + ch * 4,
                     Vtg + (size_t)row * S_LEN + kv0 + ch * 8);
            }
        }
    };

    load_kv(0, 0);   CP_COMMIT();
    load_kv(1, BKV); CP_COMMIT();

    // Q fragments (bf16 packed, pre-scaled by 0.125)
    const unsigned* Qu = (const unsigned*)
        (g_Q + ((size_t)bh * S_LEN + q0 + 16 * w) * HDIM);
    unsigned qa[4][4];
#pragma unroll
    for (int kd = 0; kd < 4; kd++) {
        qa[kd][0] = Qu[qh * 32 + kd * 8 + r];
        qa[kd][1] = Qu[(qh + 8) * 32 + kd * 8 + r];
        qa[kd][2] = Qu[qh * 32 + kd * 8 + r + 4];
        qa[kd][3] = Qu[(qh + 8) * 32 + kd * 8 + r + 4];
    }

    float o[8][4];
#pragma unroll
    for (int j = 0; j < 8; j++)
#pragma unroll
        for (int k = 0; k < 4; k++) o[j][k] = 0.0f;
    float m0 = -1e30f, m1 = -1e30f, l0 = 0.0f, l1 = 0.0f;

    const int prow0 = (16 * w + qh) * PT_STRIDE;
    const int prow1 = prow0 + 8 * PT_STRIDE;

    const int NT = S_LEN / BKV;    // 16
    for (int it = 0; it < NT; it++) {
        CP_WAIT(1);
        __syncthreads();

        const unsigned* Ku  = Kst + (it & 1) * BKV * KT_STRIDE;
        const unsigned* Vtu = Vst + (it & 1) * HDIM * VT_STRIDE;

        // ---- S = Q @ K^T ----
        float s[16][4];
#pragma unroll
        for (int j = 0; j < 16; j++)
#pragma unroll
            for (int k = 0; k < 4; k++) s[j][k] = 0.0f;

#pragma unroll
        for (int kd = 0; kd < 4; kd++) {
#pragma unroll
            for (int j = 0; j < 16; j++) {
                const int a = (8 * j + qh) * KT_STRIDE + kd * 8 + r;
                mma16(s[j], qa[kd], Ku[a], Ku[a + 4]);
            }
        }

        // ---- online softmax ----
        float mx0 = -1e30f, mx1 = -1e30f;
#pragma unroll
        for (int j = 0; j < 16; j++) {
            mx0 = fmaxf(mx0, fmaxf(s[j][0], s[j][1]));
            mx1 = fmaxf(mx1, fmaxf(s[j][2], s[j][3]));
        }
        mx0 = fmaxf(mx0, __shfl_xor_sync(0xffffffffu, mx0, 1));
        mx0 = fmaxf(mx0, __shfl_xor_sync(0xffffffffu, mx0, 2));
        mx1 = fmaxf(mx1, __shfl_xor_sync(0xffffffffu, mx1, 1));
        mx1 = fmaxf(mx1, __shfl_xor_sync(0xffffffffu, mx1, 2));

        const float n0_ = fmaxf(m0, mx0), n1_ = fmaxf(m1, mx1);
        const float c0 = __expf(m0 - n0_), c1 = __expf(m1 - n1_);
        m0 = n0_; m1 = n1_;

        float rs0 = 0.0f, rs1 = 0.0f;
#pragma unroll
        for (int j = 0; j < 16; j++) {
            s[j][0] = __expf(s[j][0] - m0);
            s[j][1] = __expf(s[j][1] - m0);
            rs0 += s[j][0] + s[j][1];
            s[j][2] = __expf(s[j][2] - m1);
            s[j][3] = __expf(s[j][3] - m1);
            rs1 += s[j][2] + s[j][3];
        }
        rs0 += __shfl_xor_sync(0xffffffffu, rs0, 1);
        rs0 += __shfl_xor_sync(0xffffffffu, rs0, 2);
        rs1 += __shfl_xor_sync(0xffffffffu, rs1, 1);
        rs1 += __shfl_xor_sync(0xffffffffu, rs1, 2);
        l0 = l0 * c0 + rs0;
        l1 = l1 * c1 + rs1;

#pragma unroll
        for (int j = 0; j < 8; j++) {
            o[j][0] *= c0; o[j][1] *= c0;
            o[j][2] *= c1; o[j][3] *= c1;
        }

        // ---- P -> warp-private smem (bf16 packed) ----
#pragma unroll
        for (int j = 0; j < 16; j++) {
            Pu[prow0 + 4 * j + r] = packbf(s[j][0], s[j][1]);
            Pu[prow1 + 4 * j + r] = packbf(s[j][2], s[j][3]);
        }
        __syncwarp();

        // ---- O += P @ V ----
#pragma unroll
        for (int kf = 0; kf < 8; kf++) {
            unsigned a[4];
            a[0] = Pu[prow0 + kf * 8 + r];
            a[1] = Pu[prow1 + kf * 8 + r];
            a[2] = Pu[prow0 + kf * 8 + r + 4];
            a[3] = Pu[prow1 + kf * 8 + r + 4];
#pragma unroll
            for (int j = 0; j < 8; j++) {
                const int vb = (8 * j + qh) * VT_STRIDE + kf * 8 + r;
                mma16(o[j], a, Vtu[vb], Vtu[vb + 4]);
            }
        }
        __syncthreads();

        if (it + 2 < NT) load_kv(it & 1, (it + 2) * BKV);
        CP_COMMIT();
    }

    // epilogue: O / l -> g_O [B,S,D] (fp32)
    const float i0 = 1.0f / l0, i1 = 1.0f / l1;
    const int b = bh >> 4, h = bh & 15;
    const int row0 = q0 + 16 * w + qh;
    float* G0 = g_O + ((size_t)b * S_LEN + row0) * D_MODEL + h * HDIM;
    float* G1 = G0 + 8 * D_MODEL;
#pragma unroll
    for (int j = 0; j < 8; j++) {
        const int cc = 8 * j + 2 * r;
        *(float2*)(G0 + cc) = make_float2(o[j][0] * i0, o[j][1] * i0);
        *(float2*)(G1 + cc) = make_float2(o[j][2] * i1, o[j][3] * i1);
    }
}

// ---------------------------------------------------------------------------
// Residual + LayerNorm. Grid: B*S rows, 256 threads (1 float4 each).
// ---------------------------------------------------------------------------
__global__ __launch_bounds__(256)
void ln_kernel(const float* __restrict__ X,
               const float* __restrict__ gamma,
               const float* __restrict__ beta,
               float* __restrict__ out)
{
    const int row = blockIdx.x;
    const int tid = threadIdx.x;

    const float4 a = ((const float4*)(g_O + (size_t)row * D_MODEL))[tid];
    const float4 b = ((const float4*)(X   + (size_t)row * D_MODEL))[tid];
    float4 v;
    v.x = a.x + b.x; v.y = a.y + b.y; v.z = a.z + b.z; v.w = a.w + b.w;

    float s  = v.x + v.y + v.z + v.w;
    float ss = v.x * v.x + v.y * v.y + v.z * v.z + v.w * v.w;

#pragma unroll
    for (int off = 16; off > 0; off >>= 1) {
        s  += __shfl_xor_sync(0xffffffffu, s,  off);
        ss += __shfl_xor_sync(0xffffffffu, ss, off);
    }

    __shared__ float sh_s[8], sh_ss[8];
    const int w = tid >> 5, lane = tid & 31;
    if (lane == 0) { sh_s[w] = s; sh_ss[w] = ss; }
    __syncthreads();

    float tot = 0.f, tot2 = 0.f;
#pragma unroll
    for (int i = 0; i < 8; i++) { tot += sh_s[i]; tot2 += sh_ss[i]; }

    const float mean = tot * (1.0f / D_MODEL);
    const float var  = tot2 * (1.0f / D_MODEL) - mean * mean;
    const float rstd = rsqrtf(var + LN_EPS);

    const float4 gg = ((const float4*)gamma)[tid];
    const float4 bb = ((const float4*)beta)[tid];
    float4 rv;
    rv.x = (v.x - mean) * rstd * gg.x + bb.x;
    rv.y = (v.y - mean) * rstd * gg.y + bb.y;
    rv.z = (v.z - mean) * rstd * gg.z + bb.z;
    rv.w = (v.w - mean) * rstd * gg.w + bb.w;
    ((float4*)out)[(size_t)row * (D_MODEL / 4) + tid] = rv;
}

// ---------------------------------------------------------------------------
// Launch
// ---------------------------------------------------------------------------
extern "C" void kernel_launch(void* const* d_in, const int* in_sizes, int n_in,
                              void* d_out, int out_size)
{
    const float* x     = (const float*)d_in[0];
    const float* wq    = (const float*)d_in[1];
    const float* bq    = (const float*)d_in[2];
    const float* wk    = (const float*)d_in[3];
    const float* bk    = (const float*)d_in[4];
    const float* wv    = (const float*)d_in[5];
    const float* bv    = (const float*)d_in[6];
    const float* gamma = (const float*)d_in[7];
    const float* beta  = (const float*)d_in[8];
    float* out = (float*)d_out;

    static bool attrs_set = false;
    if (!attrs_set) {
        cudaFuncSetAttribute(qkv_gemm,
                             cudaFuncAttributeMaxDynamicSharedMemorySize, QKV_SMEM);
        cudaFuncSetAttribute(attn_mma,
                             cudaFuncAttributeMaxDynamicSharedMemorySize, ATTN_SMEM);
        attrs_set = true;
    }

    const int ntot = XN + 3 * WN;
    cvt_kernel<<<ntot / (256 * 4), 256>>>(x, wq, wk, wv);

    dim3 ggrid(8, 32, 3);
    qkv_gemm<<<ggrid, 256, QKV_SMEM>>>(bq, bk, bv);

    dim3 agrid(S_LEN / BQ, BATCH * NHEAD);
    attn_mma<<<agrid, 256, ATTN_SMEM>>>();

    ln_kernel<<<BATCH * S_LEN, 256>>>(x, gamma, beta, out);
}